// round 3
// baseline (speedup 1.0000x reference)
#include <cuda_runtime.h>

#define NSEQ 512
#define DFEAT 48
#define DH 96
#define TPB 128

// Scratch (no allocs allowed): factored first-layer projections.
// g_A[b][i][k]  = sum_c x[b,i,c]*W1[c,k] + b1[k]            (row-major, broadcast per CTA)
// g_Bt[b][k][j] = sum_c x[b,j,c]*W1[48+c,k]                 (j-contiguous for coalesced lane loads)
__device__ float g_A[4 * NSEQ * DH];
__device__ float g_Bt[4 * DH * NSEQ];

__global__ void precompute_kernel(const float* __restrict__ x,
                                  const float* __restrict__ W1,
                                  const float* __restrict__ b1) {
    int row = blockIdx.x;            // b*N + i
    int b = row >> 9;
    int i = row & (NSEQ - 1);
    __shared__ float sx[DFEAT];
    int t = threadIdx.x;             // 0..95 (output channel k)
    if (t < DFEAT) sx[t] = x[row * DFEAT + t];
    __syncthreads();
    float a = b1[t];
    float bb = 0.f;
#pragma unroll
    for (int c = 0; c < DFEAT; c++) {
        float xv = sx[c];
        a  = fmaf(xv, W1[c * DH + t], a);
        bb = fmaf(xv, W1[(DFEAT + c) * DH + t], bb);
    }
    g_A[row * DH + t] = a;
    g_Bt[(b * DH + t) * NSEQ + i] = bb;
}

__global__ void __launch_bounds__(TPB) pair_kernel(const float* __restrict__ W2,
                                                   const float* __restrict__ b2,
                                                   float* __restrict__ out) {
    const int i = (int)(gridDim.x - 1 - blockIdx.x);   // longest rows scheduled first
    const int b = blockIdx.y;
    const int tid = threadIdx.x;

    __shared__ __align__(16) float sW2[DH * DFEAT];    // 18 KB
    __shared__ __align__(16) float sA[DH];
    __shared__ __align__(16) float sb2[DFEAT];
    __shared__ float red_m[4], red_s[4];
    __shared__ float red_o[4][DFEAT];

    for (int q = tid; q < DH * DFEAT; q += TPB) sW2[q] = W2[q];
    if (tid < DH)    sA[tid]  = g_A[(b * NSEQ + i) * DH + tid];
    if (tid < DFEAT) sb2[tid] = b2[tid];
    __syncthreads();

    const float* __restrict__ Btb = g_Bt + b * DH * NSEQ;

    // Online softmax state (per thread). o kept packed f32x2 in 24 u64 regs.
    float m = -1e30f, s = 0.f;
    unsigned long long o2[24];
#pragma unroll
    for (int q = 0; q < 24; q++) o2[q] = 0ull;

    const unsigned long long* sb2p = (const unsigned long long*)sb2;
    const ulonglong2* sW2v = (const ulonglong2*)sW2;

    for (int j = tid; j <= i; j += TPB) {
        // p[0..47] packed as 24 x f32x2, initialized to b2
        unsigned long long p2[24];
#pragma unroll
        for (int q = 0; q < 24; q++) p2[q] = sb2p[q];

#pragma unroll 2
        for (int k0 = 0; k0 < DH; k0 += 4) {
            float bv[4];
#pragma unroll
            for (int u = 0; u < 4; u++) bv[u] = Btb[(k0 + u) * NSEQ + j];
#pragma unroll
            for (int u = 0; u < 4; u++) {
                const int k = k0 + u;
                float pre = sA[k] + bv[u];
                // exact GELU (erf form, matches approximate=False)
                float h = 0.5f * pre * (1.0f + erff(pre * 0.70710678118654752f));
                unsigned long long hh;
                asm("mov.b64 %0, {%1, %1};" : "=l"(hh) : "r"(__float_as_uint(h)));
                const ulonglong2* wrow = sW2v + k * 12;   // W2 row k: 48 floats = 12 x 16B
#pragma unroll
                for (int q = 0; q < 12; q++) {
                    ulonglong2 wv = wrow[q];              // LDS.128 broadcast
                    asm("fma.rn.f32x2 %0, %1, %2, %0;" : "+l"(p2[2 * q])     : "l"(hh), "l"(wv.x));
                    asm("fma.rn.f32x2 %0, %1, %2, %0;" : "+l"(p2[2 * q + 1]) : "l"(hh), "l"(wv.y));
                }
            }
        }

        // ||p|| via packed squares
        unsigned long long n2 = 0ull;
#pragma unroll
        for (int q = 0; q < 24; q++)
            asm("fma.rn.f32x2 %0, %1, %1, %0;" : "+l"(n2) : "l"(p2[q]));
        unsigned nlo, nhi;
        asm("mov.b64 {%0, %1}, %2;" : "=r"(nlo), "=r"(nhi) : "l"(n2));
        float wgt = sqrtf(__uint_as_float(nlo) + __uint_as_float(nhi));

        // online softmax update
        float mNew = fmaxf(m, wgt);
        float c = __expf(m - mNew);
        float e = __expf(wgt - mNew);
        s = s * c + e;
        m = mNew;
        unsigned long long cc, ee;
        asm("mov.b64 %0, {%1, %1};" : "=l"(cc) : "r"(__float_as_uint(c)));
        asm("mov.b64 %0, {%1, %1};" : "=l"(ee) : "r"(__float_as_uint(e)));
#pragma unroll
        for (int q = 0; q < 24; q++) {
            asm("mul.rn.f32x2 %0, %0, %1;"     : "+l"(o2[q]) : "l"(cc));
            asm("fma.rn.f32x2 %0, %1, %2, %0;" : "+l"(o2[q]) : "l"(p2[q]), "l"(ee));
        }
    }

    // ---- reduction: warp level (shuffle), then 4 warps via shared ----
    const unsigned full = 0xffffffffu;
    float mw = m;
#pragma unroll
    for (int off = 16; off; off >>= 1)
        mw = fmaxf(mw, __shfl_xor_sync(full, mw, off));
    float scale = __expf(m - mw);       // 0 for threads with no pairs (m=-1e30)
    float sl = s * scale;
#pragma unroll
    for (int off = 16; off; off >>= 1)
        sl += __shfl_xor_sync(full, sl, off);

    unsigned long long sc2;
    asm("mov.b64 %0, {%1, %1};" : "=l"(sc2) : "r"(__float_as_uint(scale)));
#pragma unroll
    for (int q = 0; q < 24; q++)
        asm("mul.rn.f32x2 %0, %0, %1;" : "+l"(o2[q]) : "l"(sc2));
#pragma unroll
    for (int off = 16; off; off >>= 1) {
#pragma unroll
        for (int q = 0; q < 24; q++) {
            unsigned long long t = __shfl_xor_sync(full, o2[q], off);
            asm("add.rn.f32x2 %0, %0, %1;" : "+l"(o2[q]) : "l"(t));
        }
    }

    const int warp = tid >> 5;
    if ((tid & 31) == 0) {
        red_m[warp] = mw;
        red_s[warp] = sl;
#pragma unroll
        for (int q = 0; q < 24; q++) {
            unsigned lo, hi;
            asm("mov.b64 {%0, %1}, %2;" : "=r"(lo), "=r"(hi) : "l"(o2[q]));
            red_o[warp][2 * q]     = __uint_as_float(lo);
            red_o[warp][2 * q + 1] = __uint_as_float(hi);
        }
    }
    __syncthreads();

    if (tid < DFEAT) {
        float M = fmaxf(fmaxf(red_m[0], red_m[1]), fmaxf(red_m[2], red_m[3]));
        float S = 0.f, O = 0.f;
#pragma unroll
        for (int w = 0; w < 4; w++) {
            float f = __expf(red_m[w] - M);   // 0 for idle warps
            S += red_s[w] * f;
            O += red_o[w][tid] * f;
        }
        out[(b * NSEQ + i) * DFEAT + tid] = O / S;
    }
}

extern "C" void kernel_launch(void* const* d_in, const int* in_sizes, int n_in,
                              void* d_out, int out_size) {
    const float* x  = (const float*)d_in[0];
    const float* W1 = (const float*)d_in[1];
    const float* b1 = (const float*)d_in[2];
    const float* W2 = (const float*)d_in[3];
    const float* b2 = (const float*)d_in[4];
    float* out = (float*)d_out;

    precompute_kernel<<<4 * NSEQ, DH>>>(x, W1, b1);
    dim3 grid(NSEQ, 4);
    pair_kernel<<<grid, TPB>>>(W2, b2, out);
}

// round 4
// speedup vs baseline: 1.0057x; 1.0057x over previous
#include <cuda_runtime.h>

#define NSEQ 512
#define DFEAT 48
#define DH 96
#define TPB 128

// Factored first-layer projections (no allocs allowed -> device globals).
// g_A[b][i][k]  = sum_c x[b,i,c]*W1[c,k] + b1[k]
// g_Bt[b][k][j] = sum_c x[b,j,c]*W1[48+c,k]   (j-contiguous => coalesced)
__device__ float g_A[4 * NSEQ * DH];
__device__ float g_Bt[4 * DH * NSEQ];

__global__ void precompute_kernel(const float* __restrict__ x,
                                  const float* __restrict__ W1,
                                  const float* __restrict__ b1) {
    int row = blockIdx.x;            // b*N + i
    int b = row >> 9;
    int i = row & (NSEQ - 1);
    __shared__ float sx[DFEAT];
    int t = threadIdx.x;             // 0..95 (output channel k)
    if (t < DFEAT) sx[t] = x[row * DFEAT + t];
    __syncthreads();
    float a = b1[t];
    float bb = 0.f;
#pragma unroll
    for (int c = 0; c < DFEAT; c++) {
        float xv = sx[c];
        a  = fmaf(xv, W1[c * DH + t], a);
        bb = fmaf(xv, W1[(DFEAT + c) * DH + t], bb);
    }
    g_A[row * DH + t] = a;
    g_Bt[(b * DH + t) * NSEQ + i] = bb;
}

__device__ __forceinline__ float gelu_exact(float x) {
    return 0.5f * x * (1.0f + erff(x * 0.70710678118654752f));
}

__device__ __forceinline__ unsigned long long bcast2(float v) {
    unsigned long long r;
    asm("mov.b64 %0, {%1, %1};" : "=l"(r) : "r"(__float_as_uint(v)));
    return r;
}

// One CTA per output row (b,i). 128 threads = 32 j-slots x 4 feature-lanes.
// Quad lane q owns features [q*12, q*12+12). Each j-slot processes 2 j's per
// outer iteration (j_a = jbase+slot, j_b = jbase+32+slot) so each W2 chunk
// load is reused twice. h[k] is computed by lane q==k%4 and width-4 shuffled.
__global__ void __launch_bounds__(TPB) pair_kernel(const float* __restrict__ W2,
                                                   const float* __restrict__ b2,
                                                   float* __restrict__ out) {
    const int i = (int)(gridDim.x - 1 - blockIdx.x);   // longest rows first
    const int b = blockIdx.y;
    const int tid = threadIdx.x;
    const int q = tid & 3;                 // feature quarter
    const int w = tid >> 5;                // warp
    const int jslot = (w << 3) | ((tid >> 2) & 7);   // 0..31

    __shared__ __align__(16) float sW2[DH * DFEAT];  // 18 KB
    __shared__ __align__(16) float sA[DH];
    __shared__ __align__(16) float sb2[DFEAT];
    __shared__ float red_m[4], red_s[4];
    __shared__ __align__(16) float red_o[4][DFEAT];

    for (int t = tid; t < DH * DFEAT; t += TPB) sW2[t] = W2[t];
    if (tid < DH)    sA[tid]  = g_A[(b * NSEQ + i) * DH + tid];
    if (tid < DFEAT) sb2[tid] = b2[tid];
    __syncthreads();

    const float* __restrict__ Btb = g_Bt + b * DH * NSEQ;
    const unsigned long long* __restrict__ b2p =
        (const unsigned long long*)(sb2 + q * 12);   // 6 u64 = this lane's 12 feats

    float m = -1e30f, s = 0.f;
    unsigned long long o2[6];
#pragma unroll
    for (int r = 0; r < 6; r++) o2[r] = 0ull;
    const unsigned full = 0xffffffffu;

    for (int jbase = 0; jbase <= i; jbase += 64) {
        const int ja = jbase + jslot;
        const int jb = ja + 32;
        const bool va = (ja <= i);
        const bool vb = (jb <= i);
        const int jac = va ? ja : 0;     // clamp to a valid address; masked later
        const int jbc = vb ? jb : 0;

        unsigned long long p2a[6], p2b[6];
#pragma unroll
        for (int r = 0; r < 6; r++) { p2a[r] = b2p[r]; p2b[r] = b2p[r]; }

#pragma unroll 2
        for (int k0 = 0; k0 < DH; k0 += 4) {
            const int kq = k0 + q;                    // this lane's owned k
            float pa = sA[kq] + Btb[kq * NSEQ + jac];
            float pb = sA[kq] + Btb[kq * NSEQ + jbc];
            float ha = gelu_exact(pa);
            float hb = gelu_exact(pb);
#pragma unroll
            for (int u = 0; u < 4; u++) {
                float hau = __shfl_sync(full, ha, u, 4);  // from lane quadbase+u
                float hbu = __shfl_sync(full, hb, u, 4);
                unsigned long long ha2 = bcast2(hau);
                unsigned long long hb2 = bcast2(hbu);
                const ulonglong2* wr =
                    (const ulonglong2*)(sW2 + (k0 + u) * DFEAT + q * 12);
#pragma unroll
                for (int r = 0; r < 3; r++) {
                    ulonglong2 wv = wr[r];                // LDS.128, 4-addr bcast
                    asm("fma.rn.f32x2 %0, %1, %2, %0;" : "+l"(p2a[2*r])   : "l"(ha2), "l"(wv.x));
                    asm("fma.rn.f32x2 %0, %1, %2, %0;" : "+l"(p2a[2*r+1]) : "l"(ha2), "l"(wv.y));
                    asm("fma.rn.f32x2 %0, %1, %2, %0;" : "+l"(p2b[2*r])   : "l"(hb2), "l"(wv.x));
                    asm("fma.rn.f32x2 %0, %1, %2, %0;" : "+l"(p2b[2*r+1]) : "l"(hb2), "l"(wv.y));
                }
            }
        }

        // partial norms over this lane's 12 features, then quad-sum (all lanes
        // of a quad end with bitwise-identical totals -> identical m,s state)
        unsigned long long na2 = 0ull, nb2 = 0ull;
#pragma unroll
        for (int r = 0; r < 6; r++) {
            asm("fma.rn.f32x2 %0, %1, %1, %0;" : "+l"(na2) : "l"(p2a[r]));
            asm("fma.rn.f32x2 %0, %1, %1, %0;" : "+l"(nb2) : "l"(p2b[r]));
        }
        unsigned lo, hi;
        asm("mov.b64 {%0, %1}, %2;" : "=r"(lo), "=r"(hi) : "l"(na2));
        float na = __uint_as_float(lo) + __uint_as_float(hi);
        asm("mov.b64 {%0, %1}, %2;" : "=r"(lo), "=r"(hi) : "l"(nb2));
        float nb = __uint_as_float(lo) + __uint_as_float(hi);
        na += __shfl_xor_sync(full, na, 1, 4);
        na += __shfl_xor_sync(full, na, 2, 4);
        nb += __shfl_xor_sync(full, nb, 1, 4);
        nb += __shfl_xor_sync(full, nb, 2, 4);

        float wa = va ? sqrtf(na) : -1e30f;
        float wb = vb ? sqrtf(nb) : -1e30f;

        // online softmax merge of two new scores
        float mN = fmaxf(m, fmaxf(wa, wb));
        float c  = __expf(m - mN);
        float ea = __expf(wa - mN);       // 0 when masked
        float eb = __expf(wb - mN);
        s = s * c + ea + eb;
        m = mN;
        unsigned long long c2 = bcast2(c), ea2 = bcast2(ea), eb2 = bcast2(eb);
#pragma unroll
        for (int r = 0; r < 6; r++) {
            asm("mul.rn.f32x2 %0, %0, %1;"     : "+l"(o2[r]) : "l"(c2));
            asm("fma.rn.f32x2 %0, %1, %2, %0;" : "+l"(o2[r]) : "l"(p2a[r]), "l"(ea2));
            asm("fma.rn.f32x2 %0, %1, %2, %0;" : "+l"(o2[r]) : "l"(p2b[r]), "l"(eb2));
        }
    }

    // ---- reduce across the 8 j-slots in each warp (preserving q lanes) ----
#pragma unroll
    for (int off = 4; off <= 16; off <<= 1) {
        float mo = __shfl_xor_sync(full, m, off);
        float so = __shfl_xor_sync(full, s, off);
        float mN = fmaxf(m, mo);
        float fs = __expf(m - mN);
        float fo = __expf(mo - mN);
        s = s * fs + so * fo;
        unsigned long long fs2 = bcast2(fs), fo2 = bcast2(fo);
#pragma unroll
        for (int r = 0; r < 6; r++) {
            unsigned long long t = __shfl_xor_sync(full, o2[r], off);
            asm("mul.rn.f32x2 %0, %0, %1;"     : "+l"(o2[r]) : "l"(fs2));
            asm("fma.rn.f32x2 %0, %1, %2, %0;" : "+l"(o2[r]) : "l"(t), "l"(fo2));
        }
        m = mN;
    }

    const int lane = tid & 31;
    if (lane < 4) {                       // lanes 0..3 hold q=0..3 warp results
        if (lane == 0) { red_m[w] = m; red_s[w] = s; }
        unsigned long long* dst = (unsigned long long*)(&red_o[w][q * 12]);
#pragma unroll
        for (int r = 0; r < 6; r++) dst[r] = o2[r];
    }
    __syncthreads();

    if (tid < DFEAT) {
        float M = fmaxf(fmaxf(red_m[0], red_m[1]), fmaxf(red_m[2], red_m[3]));
        float S = 0.f, O = 0.f;
#pragma unroll
        for (int ww = 0; ww < 4; ww++) {
            float f = __expf(red_m[ww] - M);   // 0 for fully idle warps
            S += red_s[ww] * f;
            O += red_o[ww][tid] * f;
        }
        out[(b * NSEQ + i) * DFEAT + tid] = O / S;
    }
}

extern "C" void kernel_launch(void* const* d_in, const int* in_sizes, int n_in,
                              void* d_out, int out_size) {
    const float* x  = (const float*)d_in[0];
    const float* W1 = (const float*)d_in[1];
    const float* b1 = (const float*)d_in[2];
    const float* W2 = (const float*)d_in[3];
    const float* b2 = (const float*)d_in[4];
    float* out = (float*)d_out;

    precompute_kernel<<<4 * NSEQ, DH>>>(x, W1, b1);
    dim3 grid(NSEQ, 4);
    pair_kernel<<<grid, TPB>>>(W2, b2, out);
}

// round 5
// speedup vs baseline: 1.2422x; 1.2351x over previous
#include <cuda_runtime.h>

#define NSEQ 512
#define DFEAT 48
#define DH 96
#define TPB 128

// Factored first-layer projections (no allocs allowed -> device globals).
// g_A[b][i][k]  = sum_c x[b,i,c]*W1[c,k] + b1[k]
// g_Bt[b][k][j] = sum_c x[b,j,c]*W1[48+c,k]   (j-contiguous => LDG.128 per thread)
__device__ float g_A[4 * NSEQ * DH];
__device__ float g_Bt[4 * DH * NSEQ];

__global__ void precompute_kernel(const float* __restrict__ x,
                                  const float* __restrict__ W1,
                                  const float* __restrict__ b1) {
    int row = blockIdx.x;            // b*N + i
    int b = row >> 9;
    int i = row & (NSEQ - 1);
    __shared__ float sx[DFEAT];
    int t = threadIdx.x;             // 0..95 (output channel k)
    if (t < DFEAT) sx[t] = x[row * DFEAT + t];
    __syncthreads();
    float a = b1[t];
    float bb = 0.f;
#pragma unroll
    for (int c = 0; c < DFEAT; c++) {
        float xv = sx[c];
        a  = fmaf(xv, W1[c * DH + t], a);
        bb = fmaf(xv, W1[(DFEAT + c) * DH + t], bb);
    }
    g_A[row * DH + t] = a;
    g_Bt[(b * DH + t) * NSEQ + i] = bb;
}

__device__ __forceinline__ float gelu_exact(float x) {
    return 0.5f * x * (1.0f + erff(x * 0.70710678118654752f));
}

__device__ __forceinline__ unsigned long long bcast2(float v) {
    unsigned long long r;
    asm("mov.b64 %0, {%1, %1};" : "=l"(r) : "r"(__float_as_uint(v)));
    return r;
}

// One CTA per output row (b,i). 128 threads = 32 j-slots x 4 feature-lanes.
// Lane q owns features [q*12, q*12+12). Each j-slot owns 4 CONSECUTIVE j's
// (=> one LDG.128 per k-group). GELU h for k=k0+u is computed by lane q==u
// and exchanged through a padded, double-buffered smem stage (no shuffles).
__global__ void __launch_bounds__(TPB, 4) pair_kernel(const float* __restrict__ W2,
                                                      const float* __restrict__ b2,
                                                      float* __restrict__ out) {
    const int i = (int)(gridDim.x - 1 - blockIdx.x);   // longest rows first
    const int b = blockIdx.y;
    const int tid = threadIdx.x;
    const int q = tid & 3;                 // feature quarter / k-owner within quad
    const int w = tid >> 5;                // warp
    const int lane = tid & 31;
    const int js = lane >> 2;              // jslot within warp: 0..7
    const int jslot = (w << 3) | js;       // 0..31

    __shared__ __align__(16) float sW2[DH * DFEAT];      // 18 KB
    __shared__ __align__(16) float sA[DH];
    __shared__ __align__(16) float sb2[DFEAT];
    __shared__ __align__(16) float hstage[2][4][40][4];  // parity, warp, js*5+u, 4 j's
    __shared__ float red_m[4], red_s[4];
    __shared__ __align__(16) float red_o[4][DFEAT];

    for (int t = tid; t < DH * DFEAT; t += TPB) sW2[t] = W2[t];
    if (tid < DH)    sA[tid]  = g_A[(b * NSEQ + i) * DH + tid];
    if (tid < DFEAT) sb2[tid] = b2[tid];
    __syncthreads();

    const float* __restrict__ Btb = g_Bt + b * DH * NSEQ + q * NSEQ;  // row q base
    const unsigned long long* __restrict__ b2p =
        (const unsigned long long*)(sb2 + q * 12);   // this lane's 12 feats

    float m = -1e30f, s = 0.f;
    unsigned long long o2[6];
#pragma unroll
    for (int r = 0; r < 6; r++) o2[r] = 0ull;
    const unsigned full = 0xffffffffu;

    for (int jbase = 0; jbase <= i; jbase += 128) {
        const int j0 = jbase + (jslot << 2);          // this thread's 4 j's: j0..j0+3

        unsigned long long p2[4][6];
#pragma unroll
        for (int jt = 0; jt < 4; jt++)
#pragma unroll
            for (int r = 0; r < 6; r++) p2[jt][r] = b2p[r];

#pragma unroll 2
        for (int g = 0; g < DH / 4; g++) {
            const int k0 = g << 2;
            const int kq = k0 + q;
            // one LDG.128: Bt row kq, 4 consecutive j's (always in-bounds)
            float4 bv = *(const float4*)(Btb + (k0 << 9) + j0);  // (kq)*NSEQ = q*NSEQ pre-added
            float av = sA[kq];
            float4 h4;
            h4.x = gelu_exact(av + bv.x);
            h4.y = gelu_exact(av + bv.y);
            h4.z = gelu_exact(av + bv.z);
            h4.w = gelu_exact(av + bv.w);
            const int par = g & 1;
            *(float4*)&hstage[par][w][js * 5 + q][0] = h4;
            __syncwarp();
#pragma unroll
            for (int u = 0; u < 4; u++) {
                float4 hu = *(const float4*)&hstage[par][w][js * 5 + u][0];
                const ulonglong2* wr =
                    (const ulonglong2*)(sW2 + (k0 + u) * DFEAT + q * 12);
                float hv[4] = {hu.x, hu.y, hu.z, hu.w};
#pragma unroll
                for (int r = 0; r < 3; r++) {
                    ulonglong2 wv = wr[r];                // LDS.128 broadcast (4 addrs)
#pragma unroll
                    for (int jt = 0; jt < 4; jt++) {
                        unsigned long long h2 = bcast2(hv[jt]);
                        asm("fma.rn.f32x2 %0, %1, %2, %0;" : "+l"(p2[jt][2*r])   : "l"(h2), "l"(wv.x));
                        asm("fma.rn.f32x2 %0, %1, %2, %0;" : "+l"(p2[jt][2*r+1]) : "l"(h2), "l"(wv.y));
                    }
                }
            }
        }

        // per-j norms: own 12 features, then quad-sum (all quad lanes converge
        // to identical totals -> identical m,s trajectories)
        float wgt[4];
#pragma unroll
        for (int jt = 0; jt < 4; jt++) {
            unsigned long long n2 = 0ull;
#pragma unroll
            for (int r = 0; r < 6; r++)
                asm("fma.rn.f32x2 %0, %1, %1, %0;" : "+l"(n2) : "l"(p2[jt][r]));
            unsigned lo, hi;
            asm("mov.b64 {%0, %1}, %2;" : "=r"(lo), "=r"(hi) : "l"(n2));
            float n = __uint_as_float(lo) + __uint_as_float(hi);
            n += __shfl_xor_sync(full, n, 1, 4);
            n += __shfl_xor_sync(full, n, 2, 4);
            wgt[jt] = (j0 + jt <= i) ? sqrtf(n) : -1e30f;
        }

        // online softmax merge of 4 new scores
        float mN = fmaxf(fmaxf(wgt[0], wgt[1]), fmaxf(wgt[2], wgt[3]));
        mN = fmaxf(m, mN);
        float c = __expf(m - mN);
        float e[4];
#pragma unroll
        for (int jt = 0; jt < 4; jt++) e[jt] = __expf(wgt[jt] - mN);  // 0 if masked
        s = s * c + ((e[0] + e[1]) + (e[2] + e[3]));
        m = mN;
        unsigned long long c2 = bcast2(c);
        unsigned long long e2[4];
#pragma unroll
        for (int jt = 0; jt < 4; jt++) e2[jt] = bcast2(e[jt]);
#pragma unroll
        for (int r = 0; r < 6; r++) {
            asm("mul.rn.f32x2 %0, %0, %1;" : "+l"(o2[r]) : "l"(c2));
#pragma unroll
            for (int jt = 0; jt < 4; jt++)
                asm("fma.rn.f32x2 %0, %1, %2, %0;" : "+l"(o2[r]) : "l"(p2[jt][r]), "l"(e2[jt]));
        }
    }

    // ---- reduce across the 8 j-slots in each warp (preserving q lanes) ----
#pragma unroll
    for (int off = 4; off <= 16; off <<= 1) {
        float mo = __shfl_xor_sync(full, m, off);
        float so = __shfl_xor_sync(full, s, off);
        float mN = fmaxf(m, mo);
        float fs = __expf(m - mN);
        float fo = __expf(mo - mN);
        s = s * fs + so * fo;
        unsigned long long fs2 = bcast2(fs), fo2 = bcast2(fo);
#pragma unroll
        for (int r = 0; r < 6; r++) {
            unsigned long long t = __shfl_xor_sync(full, o2[r], off);
            asm("mul.rn.f32x2 %0, %0, %1;"     : "+l"(o2[r]) : "l"(fs2));
            asm("fma.rn.f32x2 %0, %1, %2, %0;" : "+l"(o2[r]) : "l"(t), "l"(fo2));
        }
        m = mN;
    }

    if (lane < 4) {                       // lanes 0..3 hold q=0..3 warp results
        if (lane == 0) { red_m[w] = m; red_s[w] = s; }
        unsigned long long* dst = (unsigned long long*)(&red_o[w][q * 12]);
#pragma unroll
        for (int r = 0; r < 6; r++) dst[r] = o2[r];
    }
    __syncthreads();

    if (tid < DFEAT) {
        float M = fmaxf(fmaxf(red_m[0], red_m[1]), fmaxf(red_m[2], red_m[3]));
        float S = 0.f, O = 0.f;
#pragma unroll
        for (int ww = 0; ww < 4; ww++) {
            float f = __expf(red_m[ww] - M);   // 0 for fully idle warps
            S += red_s[ww] * f;
            O += red_o[ww][tid] * f;
        }
        out[(b * NSEQ + i) * DFEAT + tid] = O / S;
    }
}

extern "C" void kernel_launch(void* const* d_in, const int* in_sizes, int n_in,
                              void* d_out, int out_size) {
    const float* x  = (const float*)d_in[0];
    const float* W1 = (const float*)d_in[1];
    const float* b1 = (const float*)d_in[2];
    const float* W2 = (const float*)d_in[3];
    const float* b2 = (const float*)d_in[4];
    float* out = (float*)d_out;

    precompute_kernel<<<4 * NSEQ, DH>>>(x, W1, b1);
    dim3 grid(NSEQ, 4);
    pair_kernel<<<grid, TPB>>>(W2, b2, out);
}

// round 6
// speedup vs baseline: 1.2758x; 1.0270x over previous
#include <cuda_runtime.h>

#define NSEQ 512
#define DFEAT 48
#define DH 96
#define TPB 128

// Factored first-layer projections (no allocs allowed -> device globals).
// g_A[b][i][k]  = sum_c x[b,i,c]*W1[c,k] + b1[k]
// g_Bt[b][k][j] = sum_c x[b,j,c]*W1[48+c,k]   (j-contiguous => LDG.128 per thread)
__device__ float g_A[4 * NSEQ * DH];
__device__ float g_Bt[4 * DH * NSEQ];

__global__ void precompute_kernel(const float* __restrict__ x,
                                  const float* __restrict__ W1,
                                  const float* __restrict__ b1) {
    int row = blockIdx.x;            // b*N + i
    int b = row >> 9;
    int i = row & (NSEQ - 1);
    __shared__ float sx[DFEAT];
    int t = threadIdx.x;             // 0..95 (output channel k)
    if (t < DFEAT) sx[t] = x[row * DFEAT + t];
    __syncthreads();
    float a = b1[t];
    float bb = 0.f;
#pragma unroll
    for (int c = 0; c < DFEAT; c++) {
        float xv = sx[c];
        a  = fmaf(xv, W1[c * DH + t], a);
        bb = fmaf(xv, W1[(DFEAT + c) * DH + t], bb);
    }
    g_A[row * DH + t] = a;
    g_Bt[(b * DH + t) * NSEQ + i] = bb;
}

__device__ __forceinline__ float gelu_exact(float x) {
    return 0.5f * x * (1.0f + erff(x * 0.70710678118654752f));
}

__device__ __forceinline__ unsigned long long bcast2(float v) {
    unsigned long long r;
    asm("mov.b64 %0, {%1, %1};" : "=l"(r) : "r"(__float_as_uint(v)));
    return r;
}

// One CTA per output row (b,i). 128 threads = 32 j-slots x 4 feature-lanes.
// Lane q owns features [q*12, q*12+12). Each j-slot owns 4 consecutive j's.
// Bt loads are software-pipelined (prefetch g+1). W2 lives in smem permuted
// [k][r][q] so each quad LDS.128 hits one 64B-contiguous wavefront. GELU h is
// exchanged via a conflict-free padded smem stage (slot = js*4+q+(js>>1)).
__global__ void __launch_bounds__(TPB, 4) pair_kernel(const float* __restrict__ W2,
                                                      const float* __restrict__ b2,
                                                      float* __restrict__ out) {
    const int i = (int)(gridDim.x - 1 - blockIdx.x);   // longest rows first
    const int b = blockIdx.y;
    const int tid = threadIdx.x;
    const int q = tid & 3;                 // feature quarter / k-owner within quad
    const int w = tid >> 5;                // warp
    const int lane = tid & 31;
    const int js = lane >> 2;              // jslot within warp: 0..7
    const int jslot = (w << 3) | js;       // 0..31
    const int hslot = js * 4 + q + (js >> 1);   // conflict-free stage slot

    __shared__ __align__(16) float sW2p[DH * DFEAT]; // permuted [k][r][q][4]
    __shared__ __align__(16) float sA[DH];
    __shared__ __align__(16) float sb2[DFEAT];
    __shared__ __align__(16) float hstage[2][4][36][4];  // parity, warp, slot, 4 j's
    __shared__ float red_m[4], red_s[4];
    __shared__ __align__(16) float red_o[4][DFEAT];

    // permuted W2 copy: dst float4 slot ((k*3+r)*4+qq) <- W2[k][qq*12+r*4 ..+3]
    for (int t = tid; t < DH * 12; t += TPB) {      // t = (k*3+r)*4+qq
        int kk = t / 12;
        int rr = (t % 12) >> 2;
        int qq = t & 3;
        *(float4*)&sW2p[t * 4] = *(const float4*)&W2[kk * DFEAT + qq * 12 + rr * 4];
    }
    if (tid < DH)    sA[tid]  = g_A[(b * NSEQ + i) * DH + tid];
    if (tid < DFEAT) sb2[tid] = b2[tid];
    __syncthreads();

    const float* __restrict__ Btb = g_Bt + b * DH * NSEQ + q * NSEQ;  // row q base
    const unsigned long long* __restrict__ b2p =
        (const unsigned long long*)(sb2 + q * 12);   // this lane's 12 feats
    const ulonglong2* __restrict__ sW2v = (const ulonglong2*)sW2p;

    float m = -1e30f, s = 0.f;
    unsigned long long o2[6];
#pragma unroll
    for (int r = 0; r < 6; r++) o2[r] = 0ull;
    const unsigned full = 0xffffffffu;

    for (int jbase = 0; jbase <= i; jbase += 128) {
        const int j0 = jbase + (jslot << 2);          // this thread's 4 j's

        unsigned long long p2[4][6];
#pragma unroll
        for (int jt = 0; jt < 4; jt++)
#pragma unroll
            for (int r = 0; r < 6; r++) p2[jt][r] = b2p[r];

        float4 cur = *(const float4*)(Btb + j0);      // prefetch g=0

#pragma unroll 2
        for (int g = 0; g < DH / 4; g++) {
            const float4 bv = cur;
            if (g < DH / 4 - 1)                        // prefetch g+1 (k0+4 rows)
                cur = *(const float4*)(Btb + ((g + 1) << 11) + j0);

            const float av = sA[(g << 2) + q];
            float4 h4;
            h4.x = gelu_exact(av + bv.x);
            h4.y = gelu_exact(av + bv.y);
            h4.z = gelu_exact(av + bv.z);
            h4.w = gelu_exact(av + bv.w);
            const int par = g & 1;
            *(float4*)&hstage[par][w][hslot][0] = h4;
            __syncwarp();

            const int wbase = g * 48 + q;              // float4 index base
#pragma unroll
            for (int u = 0; u < 4; u++) {
                float4 hu = *(const float4*)&hstage[par][w][js * 4 + u + (js >> 1)][0];
                ulonglong2 wv0 = sW2v[wbase + u * 12];
                ulonglong2 wv1 = sW2v[wbase + u * 12 + 4];
                ulonglong2 wv2 = sW2v[wbase + u * 12 + 8];
                float hv[4] = {hu.x, hu.y, hu.z, hu.w};
#pragma unroll
                for (int jt = 0; jt < 4; jt++) {
                    unsigned long long h2 = bcast2(hv[jt]);
                    asm("fma.rn.f32x2 %0, %1, %2, %0;" : "+l"(p2[jt][0]) : "l"(h2), "l"(wv0.x));
                    asm("fma.rn.f32x2 %0, %1, %2, %0;" : "+l"(p2[jt][1]) : "l"(h2), "l"(wv0.y));
                    asm("fma.rn.f32x2 %0, %1, %2, %0;" : "+l"(p2[jt][2]) : "l"(h2), "l"(wv1.x));
                    asm("fma.rn.f32x2 %0, %1, %2, %0;" : "+l"(p2[jt][3]) : "l"(h2), "l"(wv1.y));
                    asm("fma.rn.f32x2 %0, %1, %2, %0;" : "+l"(p2[jt][4]) : "l"(h2), "l"(wv2.x));
                    asm("fma.rn.f32x2 %0, %1, %2, %0;" : "+l"(p2[jt][5]) : "l"(h2), "l"(wv2.y));
                }
            }
        }

        // per-j norms: own 12 features, then quad-sum (all quad lanes converge
        // to identical totals -> identical m,s trajectories)
        float wgt[4];
#pragma unroll
        for (int jt = 0; jt < 4; jt++) {
            unsigned long long n2 = 0ull;
#pragma unroll
            for (int r = 0; r < 6; r++)
                asm("fma.rn.f32x2 %0, %1, %1, %0;" : "+l"(n2) : "l"(p2[jt][r]));
            unsigned lo, hi;
            asm("mov.b64 {%0, %1}, %2;" : "=r"(lo), "=r"(hi) : "l"(n2));
            float n = __uint_as_float(lo) + __uint_as_float(hi);
            n += __shfl_xor_sync(full, n, 1, 4);
            n += __shfl_xor_sync(full, n, 2, 4);
            wgt[jt] = (j0 + jt <= i) ? sqrtf(n) : -1e30f;
        }

        // online softmax merge of 4 new scores
        float mN = fmaxf(fmaxf(wgt[0], wgt[1]), fmaxf(wgt[2], wgt[3]));
        mN = fmaxf(m, mN);
        float c = __expf(m - mN);
        float e[4];
#pragma unroll
        for (int jt = 0; jt < 4; jt++) e[jt] = __expf(wgt[jt] - mN);  // 0 if masked
        s = s * c + ((e[0] + e[1]) + (e[2] + e[3]));
        m = mN;
        unsigned long long c2 = bcast2(c);
        unsigned long long e2[4];
#pragma unroll
        for (int jt = 0; jt < 4; jt++) e2[jt] = bcast2(e[jt]);
#pragma unroll
        for (int r = 0; r < 6; r++) {
            asm("mul.rn.f32x2 %0, %0, %1;" : "+l"(o2[r]) : "l"(c2));
#pragma unroll
            for (int jt = 0; jt < 4; jt++)
                asm("fma.rn.f32x2 %0, %1, %2, %0;" : "+l"(o2[r]) : "l"(p2[jt][r]), "l"(e2[jt]));
        }
    }

    // ---- reduce across the 8 j-slots in each warp (preserving q lanes) ----
#pragma unroll
    for (int off = 4; off <= 16; off <<= 1) {
        float mo = __shfl_xor_sync(full, m, off);
        float so = __shfl_xor_sync(full, s, off);
        float mN = fmaxf(m, mo);
        float fs = __expf(m - mN);
        float fo = __expf(mo - mN);
        s = s * fs + so * fo;
        unsigned long long fs2 = bcast2(fs), fo2 = bcast2(fo);
#pragma unroll
        for (int r = 0; r < 6; r++) {
            unsigned long long t = __shfl_xor_sync(full, o2[r], off);
            asm("mul.rn.f32x2 %0, %0, %1;"     : "+l"(o2[r]) : "l"(fs2));
            asm("fma.rn.f32x2 %0, %1, %2, %0;" : "+l"(o2[r]) : "l"(t), "l"(fo2));
        }
        m = mN;
    }

    if (lane < 4) {                       // lanes 0..3 hold q=0..3 warp results
        if (lane == 0) { red_m[w] = m; red_s[w] = s; }
        unsigned long long* dst = (unsigned long long*)(&red_o[w][q * 12]);
#pragma unroll
        for (int r = 0; r < 6; r++) dst[r] = o2[r];
    }
    __syncthreads();

    if (tid < DFEAT) {
        float M = fmaxf(fmaxf(red_m[0], red_m[1]), fmaxf(red_m[2], red_m[3]));
        float S = 0.f, O = 0.f;
#pragma unroll
        for (int ww = 0; ww < 4; ww++) {
            float f = __expf(red_m[ww] - M);   // 0 for fully idle warps
            S += red_s[ww] * f;
            O += red_o[ww][tid] * f;
        }
        out[(b * NSEQ + i) * DFEAT + tid] = O / S;
    }
}

extern "C" void kernel_launch(void* const* d_in, const int* in_sizes, int n_in,
                              void* d_out, int out_size) {
    const float* x  = (const float*)d_in[0];
    const float* W1 = (const float*)d_in[1];
    const float* b1 = (const float*)d_in[2];
    const float* W2 = (const float*)d_in[3];
    const float* b2 = (const float*)d_in[4];
    float* out = (float*)d_out;

    precompute_kernel<<<4 * NSEQ, DH>>>(x, W1, b1);
    dim3 grid(NSEQ, 4);
    pair_kernel<<<grid, TPB>>>(W2, b2, out);
}

// round 7
// speedup vs baseline: 1.3078x; 1.0251x over previous
#include <cuda_runtime.h>

#define NSEQ 512
#define DFEAT 48
#define DH 96
#define TPB 128

// Factored first-layer projections (no allocs allowed -> device globals).
// g_A[b][i][k]  = sum_c x[b,i,c]*W1[c,k] + b1[k]
// g_Bt[b][k][j] = sum_c x[b,j,c]*W1[48+c,k]   (j-contiguous => LDG.128 per thread)
__device__ float g_A[4 * NSEQ * DH];
__device__ float g_Bt[4 * DH * NSEQ];

__global__ void precompute_kernel(const float* __restrict__ x,
                                  const float* __restrict__ W1,
                                  const float* __restrict__ b1) {
    int row = blockIdx.x;            // b*N + i
    int b = row >> 9;
    int i = row & (NSEQ - 1);
    __shared__ float sx[DFEAT];
    int t = threadIdx.x;             // 0..95 (output channel k)
    if (t < DFEAT) sx[t] = x[row * DFEAT + t];
    __syncthreads();
    float a = b1[t];
    float bb = 0.f;
#pragma unroll
    for (int c = 0; c < DFEAT; c++) {
        float xv = sx[c];
        a  = fmaf(xv, W1[c * DH + t], a);
        bb = fmaf(xv, W1[(DFEAT + c) * DH + t], bb);
    }
    g_A[row * DH + t] = a;
    g_Bt[(b * DH + t) * NSEQ + i] = bb;
}

// Branchless exact-GELU: erf via Abramowitz-Stegun 7.1.26 (|err| <= 1.5e-7).
// gelu(x) = 0.5x + 0.5|x|*erf(|x|/sqrt2); no divergent paths, 11 FMA + 2 MUFU.
__device__ __forceinline__ float gelu_fast(float x) {
    float ax = fabsf(x);
    // e = exp(-x^2/2) = exp2(x^2 * -0.5*log2(e))
    float e = exp2f(x * x * -0.72134752044448170368f);
    // k = 1/(1 + 0.3275911*(|x|/sqrt2)) ; constant prefolded by 1/sqrt2
    float kd = fmaf(0.23164408767166038f, ax, 1.0f);
    float k;
    asm("rcp.approx.f32 %0, %1;" : "=f"(k) : "f"(kd));
    float q = fmaf(k, 1.061405429f, -1.453152027f);
    q = fmaf(k, q, 1.421413741f);
    q = fmaf(k, q, -0.284496736f);
    q = fmaf(k, q, 0.254829592f);
    float E = fmaf(-(k * q), e, 1.0f);        // erf(|x|/sqrt2)
    return fmaf(0.5f * ax, E, 0.5f * x);
}

__device__ __forceinline__ unsigned long long bcast2(float v) {
    unsigned long long r;
    asm("mov.b64 %0, {%1, %1};" : "=l"(r) : "r"(__float_as_uint(v)));
    return r;
}

// One CTA per output row (b,i). 128 threads = 32 j-slots x 4 feature-lanes.
// Lane q owns features [q*12, q*12+12). Each j-slot owns 4 consecutive j's.
// Bt loads are software-pipelined (prefetch g+1). W2 lives in smem permuted
// [k][r][q] so each quad LDS.128 hits one 64B-contiguous wavefront. GELU h is
// exchanged via a conflict-free padded smem stage (slot = js*4+q+(js>>1)).
__global__ void __launch_bounds__(TPB, 4) pair_kernel(const float* __restrict__ W2,
                                                      const float* __restrict__ b2,
                                                      float* __restrict__ out) {
    const int i = (int)(gridDim.x - 1 - blockIdx.x);   // longest rows first
    const int b = blockIdx.y;
    const int tid = threadIdx.x;
    const int q = tid & 3;                 // feature quarter / k-owner within quad
    const int w = tid >> 5;                // warp
    const int lane = tid & 31;
    const int js = lane >> 2;              // jslot within warp: 0..7
    const int jslot = (w << 3) | js;       // 0..31
    const int hslot = js * 4 + q + (js >> 1);   // conflict-free stage slot

    __shared__ __align__(16) float sW2p[DH * DFEAT]; // permuted [k][r][q][4]
    __shared__ __align__(16) float sA[DH];
    __shared__ __align__(16) float sb2[DFEAT];
    __shared__ __align__(16) float hstage[2][4][36][4];  // parity, warp, slot, 4 j's
    __shared__ float red_m[4], red_s[4];
    __shared__ __align__(16) float red_o[4][DFEAT];

    // permuted W2 copy: dst float4 slot ((k*3+r)*4+qq) <- W2[k][qq*12+r*4 ..+3]
    for (int t = tid; t < DH * 12; t += TPB) {      // t = (k*3+r)*4+qq
        int kk = t / 12;
        int rr = (t % 12) >> 2;
        int qq = t & 3;
        *(float4*)&sW2p[t * 4] = *(const float4*)&W2[kk * DFEAT + qq * 12 + rr * 4];
    }
    if (tid < DH)    sA[tid]  = g_A[(b * NSEQ + i) * DH + tid];
    if (tid < DFEAT) sb2[tid] = b2[tid];
    __syncthreads();

    const float* __restrict__ Btb = g_Bt + b * DH * NSEQ + q * NSEQ;  // row q base
    const unsigned long long* __restrict__ b2p =
        (const unsigned long long*)(sb2 + q * 12);   // this lane's 12 feats
    const ulonglong2* __restrict__ sW2v = (const ulonglong2*)sW2p;

    float m = -1e30f, s = 0.f;
    unsigned long long o2[6];
#pragma unroll
    for (int r = 0; r < 6; r++) o2[r] = 0ull;
    const unsigned full = 0xffffffffu;

    for (int jbase = 0; jbase <= i; jbase += 128) {
        const int j0 = jbase + (jslot << 2);          // this thread's 4 j's

        unsigned long long p2[4][6];
#pragma unroll
        for (int jt = 0; jt < 4; jt++)
#pragma unroll
            for (int r = 0; r < 6; r++) p2[jt][r] = b2p[r];

        float4 cur = *(const float4*)(Btb + j0);      // prefetch g=0

#pragma unroll 2
        for (int g = 0; g < DH / 4; g++) {
            const float4 bv = cur;
            if (g < DH / 4 - 1)                        // prefetch g+1 (k0+4 rows)
                cur = *(const float4*)(Btb + ((g + 1) << 11) + j0);

            const float av = sA[(g << 2) + q];
            float4 h4;
            h4.x = gelu_fast(av + bv.x);
            h4.y = gelu_fast(av + bv.y);
            h4.z = gelu_fast(av + bv.z);
            h4.w = gelu_fast(av + bv.w);
            const int par = g & 1;
            *(float4*)&hstage[par][w][hslot][0] = h4;
            __syncwarp();

            const int wbase = g * 48 + q;              // float4 index base
#pragma unroll
            for (int u = 0; u < 4; u++) {
                float4 hu = *(const float4*)&hstage[par][w][js * 4 + u + (js >> 1)][0];
                ulonglong2 wv0 = sW2v[wbase + u * 12];
                ulonglong2 wv1 = sW2v[wbase + u * 12 + 4];
                ulonglong2 wv2 = sW2v[wbase + u * 12 + 8];
                float hv[4] = {hu.x, hu.y, hu.z, hu.w};
#pragma unroll
                for (int jt = 0; jt < 4; jt++) {
                    unsigned long long h2 = bcast2(hv[jt]);
                    asm("fma.rn.f32x2 %0, %1, %2, %0;" : "+l"(p2[jt][0]) : "l"(h2), "l"(wv0.x));
                    asm("fma.rn.f32x2 %0, %1, %2, %0;" : "+l"(p2[jt][1]) : "l"(h2), "l"(wv0.y));
                    asm("fma.rn.f32x2 %0, %1, %2, %0;" : "+l"(p2[jt][2]) : "l"(h2), "l"(wv1.x));
                    asm("fma.rn.f32x2 %0, %1, %2, %0;" : "+l"(p2[jt][3]) : "l"(h2), "l"(wv1.y));
                    asm("fma.rn.f32x2 %0, %1, %2, %0;" : "+l"(p2[jt][4]) : "l"(h2), "l"(wv2.x));
                    asm("fma.rn.f32x2 %0, %1, %2, %0;" : "+l"(p2[jt][5]) : "l"(h2), "l"(wv2.y));
                }
            }
        }

        // per-j norms: own 12 features, then quad-sum (all quad lanes converge
        // to identical totals -> identical m,s trajectories)
        float wgt[4];
#pragma unroll
        for (int jt = 0; jt < 4; jt++) {
            unsigned long long n2 = 0ull;
#pragma unroll
            for (int r = 0; r < 6; r++)
                asm("fma.rn.f32x2 %0, %1, %1, %0;" : "+l"(n2) : "l"(p2[jt][r]));
            unsigned lo, hi;
            asm("mov.b64 {%0, %1}, %2;" : "=r"(lo), "=r"(hi) : "l"(n2));
            float n = __uint_as_float(lo) + __uint_as_float(hi);
            n += __shfl_xor_sync(full, n, 1, 4);
            n += __shfl_xor_sync(full, n, 2, 4);
            wgt[jt] = (j0 + jt <= i) ? sqrtf(n) : -1e30f;
        }

        // online softmax merge of 4 new scores
        float mN = fmaxf(fmaxf(wgt[0], wgt[1]), fmaxf(wgt[2], wgt[3]));
        mN = fmaxf(m, mN);
        float c = __expf(m - mN);
        float e[4];
#pragma unroll
        for (int jt = 0; jt < 4; jt++) e[jt] = __expf(wgt[jt] - mN);  // 0 if masked
        s = s * c + ((e[0] + e[1]) + (e[2] + e[3]));
        m = mN;
        unsigned long long c2 = bcast2(c);
        unsigned long long e2[4];
#pragma unroll
        for (int jt = 0; jt < 4; jt++) e2[jt] = bcast2(e[jt]);
#pragma unroll
        for (int r = 0; r < 6; r++) {
            asm("mul.rn.f32x2 %0, %0, %1;" : "+l"(o2[r]) : "l"(c2));
#pragma unroll
            for (int jt = 0; jt < 4; jt++)
                asm("fma.rn.f32x2 %0, %1, %2, %0;" : "+l"(o2[r]) : "l"(p2[jt][r]), "l"(e2[jt]));
        }
    }

    // ---- reduce across the 8 j-slots in each warp (preserving q lanes) ----
#pragma unroll
    for (int off = 4; off <= 16; off <<= 1) {
        float mo = __shfl_xor_sync(full, m, off);
        float so = __shfl_xor_sync(full, s, off);
        float mN = fmaxf(m, mo);
        float fs = __expf(m - mN);
        float fo = __expf(mo - mN);
        s = s * fs + so * fo;
        unsigned long long fs2 = bcast2(fs), fo2 = bcast2(fo);
#pragma unroll
        for (int r = 0; r < 6; r++) {
            unsigned long long t = __shfl_xor_sync(full, o2[r], off);
            asm("mul.rn.f32x2 %0, %0, %1;"     : "+l"(o2[r]) : "l"(fs2));
            asm("fma.rn.f32x2 %0, %1, %2, %0;" : "+l"(o2[r]) : "l"(t), "l"(fo2));
        }
        m = mN;
    }

    if (lane < 4) {                       // lanes 0..3 hold q=0..3 warp results
        if (lane == 0) { red_m[w] = m; red_s[w] = s; }
        unsigned long long* dst = (unsigned long long*)(&red_o[w][q * 12]);
#pragma unroll
        for (int r = 0; r < 6; r++) dst[r] = o2[r];
    }
    __syncthreads();

    if (tid < DFEAT) {
        float M = fmaxf(fmaxf(red_m[0], red_m[1]), fmaxf(red_m[2], red_m[3]));
        float S = 0.f, O = 0.f;
#pragma unroll
        for (int ww = 0; ww < 4; ww++) {
            float f = __expf(red_m[ww] - M);   // 0 for fully idle warps
            S += red_s[ww] * f;
            O += red_o[ww][tid] * f;
        }
        out[(b * NSEQ + i) * DFEAT + tid] = O / S;
    }
}

extern "C" void kernel_launch(void* const* d_in, const int* in_sizes, int n_in,
                              void* d_out, int out_size) {
    const float* x  = (const float*)d_in[0];
    const float* W1 = (const float*)d_in[1];
    const float* b1 = (const float*)d_in[2];
    const float* W2 = (const float*)d_in[3];
    const float* b2 = (const float*)d_in[4];
    float* out = (float*)d_out;

    precompute_kernel<<<4 * NSEQ, DH>>>(x, W1, b1);
    dim3 grid(NSEQ, 4);
    pair_kernel<<<grid, TPB>>>(W2, b2, out);
}